// round 13
// baseline (speedup 1.0000x reference)
#include <cuda_runtime.h>

// x[512,1024,64], W*[128,192], b*[128], Wfc[10,128], bfc[10], out[512,10] fp32.
#define B_TOT    512
#define T_LEN    1024
#define I_DIM    64
#define H_DIM    128
#define C_DIM    10
#define KDIM     192            // I + H
#define BPC      4              // batch rows per CTA
#define NTHREADS 256
#define NCTAS    (B_TOT / BPC)  // 128

#define KREG     96             // k in [0,96): weights in registers
#define KSM      96             // k in [96,192): weights fp32 in SMEM
#define WSTRIDE  100            // floats per row in SMEM (400B: 25 mod 8 = 1 -> conflict-free)

// SMEM layout (floats):
//  WsmA [256][WSTRIDE]  : row0 weights (f or o), k in [96,192)
//  WsmB [256][WSTRIDE]  : row1 weights (i or g), k in [96,192)
//  acts [BPC][KDIM]     : [x_t | h_t] per batch
#define WSMA_OFF   0
#define WSMB_OFF   (256 * WSTRIDE)
#define ACTS_OFF   (2 * 256 * WSTRIDE)
#define SM_FLOATS  (ACTS_OFF + BPC * KDIM)
#define SM_TOTAL   (SM_FLOATS * 4)          // 207872 bytes

// Packed dual-fp32 FMA (Blackwell f32x2): d = a*b + c elementwise on pairs.
__device__ __forceinline__ float2 ffma2(float2 a, float2 b, float2 c) {
    float2 d;
    asm("{\n\t"
        ".reg .b64 ra, rb, rc, rd;\n\t"
        "mov.b64 ra, {%2, %3};\n\t"
        "mov.b64 rb, {%4, %5};\n\t"
        "mov.b64 rc, {%6, %7};\n\t"
        "fma.rn.f32x2 rd, ra, rb, rc;\n\t"
        "mov.b64 {%0, %1}, rd;\n\t"
        "}"
        : "=f"(d.x), "=f"(d.y)
        : "f"(a.x), "f"(a.y), "f"(b.x), "f"(b.y), "f"(c.x), "f"(c.y));
    return d;
}

__global__ void __launch_bounds__(NTHREADS, 1)
lstm_persistent_kernel(const float* __restrict__ x,
                       const float* __restrict__ Wf, const float* __restrict__ bf,
                       const float* __restrict__ Wo, const float* __restrict__ bo,
                       const float* __restrict__ Wi, const float* __restrict__ bi,
                       const float* __restrict__ Wg, const float* __restrict__ bg,
                       const float* __restrict__ Wfc, const float* __restrict__ bfc,
                       float* __restrict__ out)
{
    extern __shared__ float smem[];
    float* WsmA = smem + WSMA_OFF;
    float* WsmB = smem + WSMB_OFF;
    float* acts = smem + ACTS_OFF;   // [BPC][KDIM]

    const int tid  = threadIdx.x;
    const int b0   = blockIdx.x * BPC;
    const int col  = tid >> 1;       // h-column 0..127
    const int role = tid & 1;        // 0: (f,i), 1: (o,g)

    // Gate row sources for this thread (local row index = col in each gate matrix).
    const float* src0 = role ? Wo : Wf;   // row0
    const float* src1 = role ? Wg : Wi;   // row1
    const float  bias0 = role ? bo[col] : bf[col];
    const float  bias1 = role ? bg[col] : bi[col];

    // ---- One-time: load k<96 weights into registers (fp32, no conversion ever) ----
    float2 wr0[KREG / 2], wr1[KREG / 2];
    {
        const float4* s0 = reinterpret_cast<const float4*>(src0 + (size_t)col * KDIM);
        const float4* s1 = reinterpret_cast<const float4*>(src1 + (size_t)col * KDIM);
#pragma unroll
        for (int q = 0; q < KREG / 4; ++q) {
            float4 v0 = __ldg(s0 + q);
            float4 v1 = __ldg(s1 + q);
            wr0[2 * q + 0] = make_float2(v0.x, v0.y);
            wr0[2 * q + 1] = make_float2(v0.z, v0.w);
            wr1[2 * q + 0] = make_float2(v1.x, v1.y);
            wr1[2 * q + 1] = make_float2(v1.z, v1.w);
        }
    }

    // ---- One-time: stage k in [96,192) weights fp32 into SMEM (per-thread blocks) ----
    {
        float4*       dA = reinterpret_cast<float4*>(WsmA + tid * WSTRIDE);
        float4*       dB = reinterpret_cast<float4*>(WsmB + tid * WSTRIDE);
        const float4* sA = reinterpret_cast<const float4*>(src0 + (size_t)col * KDIM + KREG);
        const float4* sB = reinterpret_cast<const float4*>(src1 + (size_t)col * KDIM + KREG);
#pragma unroll
        for (int q = 0; q < KSM / 4; ++q) {
            dA[q] = __ldg(sA + q);
            dB[q] = __ldg(sB + q);
        }
    }

    // ---- Init activations: x(t=0), h = 0 ----
    for (int idx = tid; idx < BPC * H_DIM; idx += NTHREADS) {
        int b = idx >> 7, j = idx & 127;
        acts[b * KDIM + I_DIM + j] = 0.0f;
    }
    for (int idx = tid; idx < BPC * I_DIM; idx += NTHREADS) {
        int b = idx >> 6, i = idx & 63;
        acts[b * KDIM + i] = x[((size_t)(b0 + b) * T_LEN + 0) * I_DIM + i];
    }

    float c_state[BPC];
#pragma unroll
    for (int b = 0; b < BPC; ++b) c_state[b] = 0.0f;

    // x prefetch slot: each thread owns one element (batch bx, feature ix).
    const int bx = tid >> 6;
    const int ix = tid & 63;
    const float* xsrc = x + (size_t)(b0 + bx) * T_LEN * I_DIM + ix;

    // activation helper constants per role (branchless sigmoid/tanh):
    //   role0: sigma(z) = 1/(1+e^-z)            (m1=1, m2=1, m3=0)
    //   role1 second gate: tanh(z) = 2/(1+e^-2z) - 1 (m1=2, m2=2, m3=1)
    const float m1 = role ? 2.0f : 1.0f;
    const float m2 = role ? 2.0f : 1.0f;
    const float m3 = role ? 1.0f : 0.0f;

    const float4* wa = reinterpret_cast<const float4*>(WsmA + tid * WSTRIDE);
    const float4* wb = reinterpret_cast<const float4*>(WsmB + tid * WSTRIDE);

    __syncthreads();

    for (int t = 0; t < T_LEN; ++t) {
        float xnext = 0.0f;
        if (t + 1 < T_LEN) xnext = __ldg(xsrc + (size_t)(t + 1) * I_DIM);

        float2 acc0[BPC], acc1[BPC];
#pragma unroll
        for (int b = 0; b < BPC; ++b) {
            acc0[b] = make_float2(0.0f, 0.0f);
            acc1[b] = make_float2(0.0f, 0.0f);
        }

        // ---- Part 1: k in [0,96), weights in registers (no LDS, no converts) ----
#pragma unroll
        for (int kc = 0; kc < KREG / 8; ++kc) {
#pragma unroll
            for (int b = 0; b < BPC; ++b) {
                const float4* ap = reinterpret_cast<const float4*>(acts + b * KDIM + kc * 8);
                float4 A0 = ap[0];
                float4 A1 = ap[1];
                float2 p0 = make_float2(A0.x, A0.y);
                float2 p1 = make_float2(A0.z, A0.w);
                float2 p2 = make_float2(A1.x, A1.y);
                float2 p3 = make_float2(A1.z, A1.w);
                acc0[b] = ffma2(wr0[kc * 4 + 0], p0, acc0[b]);
                acc0[b] = ffma2(wr0[kc * 4 + 1], p1, acc0[b]);
                acc0[b] = ffma2(wr0[kc * 4 + 2], p2, acc0[b]);
                acc0[b] = ffma2(wr0[kc * 4 + 3], p3, acc0[b]);
                acc1[b] = ffma2(wr1[kc * 4 + 0], p0, acc1[b]);
                acc1[b] = ffma2(wr1[kc * 4 + 1], p1, acc1[b]);
                acc1[b] = ffma2(wr1[kc * 4 + 2], p2, acc1[b]);
                acc1[b] = ffma2(wr1[kc * 4 + 3], p3, acc1[b]);
            }
        }

        // ---- Part 2: k in [96,192), weights fp32 from SMEM ----
#pragma unroll 2
        for (int kc = 0; kc < KSM / 8; ++kc) {
            float4 u0a = wa[kc * 2 + 0];
            float4 u0b = wa[kc * 2 + 1];
            float4 u1a = wb[kc * 2 + 0];
            float4 u1b = wb[kc * 2 + 1];
            float2 w00 = make_float2(u0a.x, u0a.y);
            float2 w01 = make_float2(u0a.z, u0a.w);
            float2 w02 = make_float2(u0b.x, u0b.y);
            float2 w03 = make_float2(u0b.z, u0b.w);
            float2 w10 = make_float2(u1a.x, u1a.y);
            float2 w11 = make_float2(u1a.z, u1a.w);
            float2 w12 = make_float2(u1b.x, u1b.y);
            float2 w13 = make_float2(u1b.z, u1b.w);
#pragma unroll
            for (int b = 0; b < BPC; ++b) {
                const float4* ap = reinterpret_cast<const float4*>(acts + b * KDIM + KREG + kc * 8);
                float4 A0 = ap[0];
                float4 A1 = ap[1];
                float2 p0 = make_float2(A0.x, A0.y);
                float2 p1 = make_float2(A0.z, A0.w);
                float2 p2 = make_float2(A1.x, A1.y);
                float2 p3 = make_float2(A1.z, A1.w);
                acc0[b] = ffma2(w00, p0, acc0[b]);
                acc0[b] = ffma2(w01, p1, acc0[b]);
                acc0[b] = ffma2(w02, p2, acc0[b]);
                acc0[b] = ffma2(w03, p3, acc0[b]);
                acc1[b] = ffma2(w10, p0, acc1[b]);
                acc1[b] = ffma2(w11, p1, acc1[b]);
                acc1[b] = ffma2(w12, p2, acc1[b]);
                acc1[b] = ffma2(w13, p3, acc1[b]);
            }
        }

        __syncthreads();   // all acts reads done before anyone writes acts

        // ---- Elementwise + intra-warp (f,i)<->(o,g) exchange via shfl ----
#pragma unroll
        for (int b = 0; b < BPC; ++b) {
            float p0 = acc0[b].x + acc0[b].y + bias0;      // f or o preact
            float p1 = acc1[b].x + acc1[b].y + bias1;      // i or g preact
            float a0 = 1.0f / (1.0f + __expf(-p0));        // sigma: fs or os
            float a1 = m2 / (1.0f + __expf(-p1 * m1)) - m3; // is (sigma) or gt (tanh)
            float o0 = __shfl_xor_sync(0xFFFFFFFFu, a0, 1);
            float o1 = __shfl_xor_sync(0xFFFFFFFFu, a1, 1);
            float fs = role ? o0 : a0;
            float is = role ? o1 : a1;
            float os = role ? a0 : o0;
            float gt = role ? a1 : o1;
            float c  = c_state[b] * fs + gt * is;
            c_state[b] = c;
            float h  = c * os;
            // role0 writes batches 0,1; role1 writes batches 2,3 (identical values)
            if ((b < 2) == (role == 0))
                acts[b * KDIM + I_DIM + col] = h;
        }
        if (t + 1 < T_LEN) acts[bx * KDIM + ix] = xnext;   // stage x_{t+1}

        __syncthreads();   // h and x visible for next step
    }

    // ---- Final FC: out[b, c] = h[b,:] . Wfc[c,:] + bfc[c] ----
    for (int idx = tid; idx < BPC * C_DIM; idx += NTHREADS) {
        int b  = idx / C_DIM;
        int cc = idx - b * C_DIM;
        float s = bfc[cc];
        const float* hrow = acts + b * KDIM + I_DIM;
        const float* wrow = Wfc + cc * H_DIM;
#pragma unroll 8
        for (int k = 0; k < H_DIM; ++k)
            s += hrow[k] * wrow[k];
        out[(b0 + b) * C_DIM + cc] = s;
    }
}

extern "C" void kernel_launch(void* const* d_in, const int* in_sizes, int n_in,
                              void* d_out, int out_size)
{
    const float* x   = (const float*)d_in[0];
    const float* Wf  = (const float*)d_in[1];
    const float* bf  = (const float*)d_in[2];
    const float* Wo  = (const float*)d_in[3];
    const float* bo  = (const float*)d_in[4];
    const float* Wi  = (const float*)d_in[5];
    const float* bi  = (const float*)d_in[6];
    const float* Wg  = (const float*)d_in[7];
    const float* bg  = (const float*)d_in[8];
    const float* Wfc = (const float*)d_in[9];
    const float* bfc = (const float*)d_in[10];
    float* out = (float*)d_out;

    static bool attr_set = false;
    if (!attr_set) {
        cudaFuncSetAttribute(lstm_persistent_kernel,
                             cudaFuncAttributeMaxDynamicSharedMemorySize, SM_TOTAL);
        attr_set = true;
    }

    lstm_persistent_kernel<<<NCTAS, NTHREADS, SM_TOTAL>>>(
        x, Wf, bf, Wo, bo, Wi, bi, Wg, bg, Wfc, bfc, out);
}

// round 14
// speedup vs baseline: 1.0943x; 1.0943x over previous
#include <cuda_runtime.h>

// x[512,1024,64], W*[128,192], b*[128], Wfc[10,128], bfc[10], out[512,10] fp32.
#define B_TOT    512
#define T_LEN    1024
#define I_DIM    64
#define H_DIM    128
#define C_DIM    10
#define KDIM     192            // I + H
#define BPC      4              // batch rows per CTA
#define NTHREADS 256
#define NCTAS    (B_TOT / BPC)  // 128

#define KREG     96             // k in [0,96): weights in registers
#define KSM      96             // k in [96,192): weights fp32 in SMEM
#define WSTRIDE  100            // floats per row (400B = 25*16B, odd -> conflict-free LDS.128)

// SMEM layout (floats):
//  WsmA [256][WSTRIDE] : row0 weights (f or o), k in [96,192)
//  WsmB [256][WSTRIDE] : row1 weights (i or g), k in [96,192)
//  actsA/actsB [BPC][KDIM] : double-buffered [x_t | h_t]
#define WSMA_OFF   0
#define WSMB_OFF   (256 * WSTRIDE)
#define ACTSA_OFF  (2 * 256 * WSTRIDE)
#define ACTSB_OFF  (ACTSA_OFF + BPC * KDIM)
#define SM_FLOATS  (ACTSB_OFF + BPC * KDIM)
#define SM_TOTAL   (SM_FLOATS * 4)          // 210944 bytes

// Packed dual-fp32 FMA (Blackwell f32x2): d = a*b + c elementwise on pairs.
__device__ __forceinline__ float2 ffma2(float2 a, float2 b, float2 c) {
    float2 d;
    asm("{\n\t"
        ".reg .b64 ra, rb, rc, rd;\n\t"
        "mov.b64 ra, {%2, %3};\n\t"
        "mov.b64 rb, {%4, %5};\n\t"
        "mov.b64 rc, {%6, %7};\n\t"
        "fma.rn.f32x2 rd, ra, rb, rc;\n\t"
        "mov.b64 {%0, %1}, rd;\n\t"
        "}"
        : "=f"(d.x), "=f"(d.y)
        : "f"(a.x), "f"(a.y), "f"(b.x), "f"(b.y), "f"(c.x), "f"(c.y));
    return d;
}

// Single-MUFU tanh (sm_75+): MUFU.TANH.
__device__ __forceinline__ float tanh_mufu(float z) {
    float r;
    asm("tanh.approx.f32 %0, %1;" : "=f"(r) : "f"(z));
    return r;
}

__global__ void __launch_bounds__(NTHREADS, 1)
lstm_persistent_kernel(const float* __restrict__ x,
                       const float* __restrict__ Wf, const float* __restrict__ bf,
                       const float* __restrict__ Wo, const float* __restrict__ bo,
                       const float* __restrict__ Wi, const float* __restrict__ bi,
                       const float* __restrict__ Wg, const float* __restrict__ bg,
                       const float* __restrict__ Wfc, const float* __restrict__ bfc,
                       float* __restrict__ out)
{
    extern __shared__ float smem[];
    float* WsmA  = smem + WSMA_OFF;
    float* WsmB  = smem + WSMB_OFF;
    float* actsR = smem + ACTSA_OFF;   // read buffer (t)
    float* actsW = smem + ACTSB_OFF;   // write buffer (t+1)

    const int tid  = threadIdx.x;
    const int b0   = blockIdx.x * BPC;
    const int col  = tid >> 1;       // h-column 0..127
    const int role = tid & 1;        // 0: (f,i), 1: (o,g)

    const float* src0 = role ? Wo : Wf;   // row0
    const float* src1 = role ? Wg : Wi;   // row1
    const float  bias0 = role ? bo[col] : bf[col];
    const float  bias1 = role ? bg[col] : bi[col];

    // ---- One-time: k<96 weights into registers ----
    float2 wr0[KREG / 2], wr1[KREG / 2];
    {
        const float4* s0 = reinterpret_cast<const float4*>(src0 + (size_t)col * KDIM);
        const float4* s1 = reinterpret_cast<const float4*>(src1 + (size_t)col * KDIM);
#pragma unroll
        for (int q = 0; q < KREG / 4; ++q) {
            float4 v0 = __ldg(s0 + q);
            float4 v1 = __ldg(s1 + q);
            wr0[2 * q + 0] = make_float2(v0.x, v0.y);
            wr0[2 * q + 1] = make_float2(v0.z, v0.w);
            wr1[2 * q + 0] = make_float2(v1.x, v1.y);
            wr1[2 * q + 1] = make_float2(v1.z, v1.w);
        }
    }

    // ---- One-time: k in [96,192) weights fp32 into SMEM (per-thread blocks) ----
    {
        float4*       dA = reinterpret_cast<float4*>(WsmA + tid * WSTRIDE);
        float4*       dB = reinterpret_cast<float4*>(WsmB + tid * WSTRIDE);
        const float4* sA = reinterpret_cast<const float4*>(src0 + (size_t)col * KDIM + KREG);
        const float4* sB = reinterpret_cast<const float4*>(src1 + (size_t)col * KDIM + KREG);
#pragma unroll
        for (int q = 0; q < KSM / 4; ++q) {
            dA[q] = __ldg(sA + q);
            dB[q] = __ldg(sB + q);
        }
    }

    // ---- Init read buffer: x(t=0), h = 0 ----
    for (int idx = tid; idx < BPC * H_DIM; idx += NTHREADS) {
        int b = idx >> 7, j = idx & 127;
        actsR[b * KDIM + I_DIM + j] = 0.0f;
    }
    for (int idx = tid; idx < BPC * I_DIM; idx += NTHREADS) {
        int b = idx >> 6, i = idx & 63;
        actsR[b * KDIM + i] = x[((size_t)(b0 + b) * T_LEN + 0) * I_DIM + i];
    }

    float c_state[BPC];
#pragma unroll
    for (int b = 0; b < BPC; ++b) c_state[b] = 0.0f;

    // x prefetch slot: one element per thread (batch bx, feature ix).
    const int bx = tid >> 6;
    const int ix = tid & 63;
    const float* xsrc = x + (size_t)(b0 + bx) * T_LEN * I_DIM + ix;

    // Activation constants: sigmoid(z)=0.5*tanh(0.5z)+0.5 ; tanh(z)=tanh(z).
    // Gate1 (acc1) is sigmoid for role0 (i), tanh for role1 (g).
    const float mh = role ? 1.0f : 0.5f;   // pre-scale
    const float ms = role ? 1.0f : 0.5f;   // post-scale
    const float mc = role ? 0.0f : 0.5f;   // post-offset

    const float4* wa = reinterpret_cast<const float4*>(WsmA + tid * WSTRIDE);
    const float4* wb = reinterpret_cast<const float4*>(WsmB + tid * WSTRIDE);

    __syncthreads();

    for (int t = 0; t < T_LEN; ++t) {
        float xnext = 0.0f;
        if (t + 1 < T_LEN) xnext = __ldg(xsrc + (size_t)(t + 1) * I_DIM);

        float2 acc0[BPC], acc1[BPC];
#pragma unroll
        for (int b = 0; b < BPC; ++b) {
            acc0[b] = make_float2(0.0f, 0.0f);
            acc1[b] = make_float2(0.0f, 0.0f);
        }

        // ---- Fused GEMM: per K-chunk, SMEM weight loads overlap register-weight FMAs ----
#pragma unroll
        for (int kc = 0; kc < 12; ++kc) {
            // Issue SMEM weight loads for this chunk first (latency hidden below).
            float4 u0a = wa[kc * 2 + 0];
            float4 u0b = wa[kc * 2 + 1];
            float4 u1a = wb[kc * 2 + 0];
            float4 u1b = wb[kc * 2 + 1];

            // Register-weight FMAs, acts k in [kc*8, kc*8+8)
#pragma unroll
            for (int b = 0; b < BPC; ++b) {
                const float4* ap = reinterpret_cast<const float4*>(actsR + b * KDIM + kc * 8);
                float4 A0 = ap[0];
                float4 A1 = ap[1];
                float2 p0 = make_float2(A0.x, A0.y);
                float2 p1 = make_float2(A0.z, A0.w);
                float2 p2 = make_float2(A1.x, A1.y);
                float2 p3 = make_float2(A1.z, A1.w);
                acc0[b] = ffma2(wr0[kc * 4 + 0], p0, acc0[b]);
                acc0[b] = ffma2(wr0[kc * 4 + 1], p1, acc0[b]);
                acc0[b] = ffma2(wr0[kc * 4 + 2], p2, acc0[b]);
                acc0[b] = ffma2(wr0[kc * 4 + 3], p3, acc0[b]);
                acc1[b] = ffma2(wr1[kc * 4 + 0], p0, acc1[b]);
                acc1[b] = ffma2(wr1[kc * 4 + 1], p1, acc1[b]);
                acc1[b] = ffma2(wr1[kc * 4 + 2], p2, acc1[b]);
                acc1[b] = ffma2(wr1[kc * 4 + 3], p3, acc1[b]);
            }

            // SMEM-weight FMAs, acts k in [96+kc*8, 96+kc*8+8)
            float2 w00 = make_float2(u0a.x, u0a.y);
            float2 w01 = make_float2(u0a.z, u0a.w);
            float2 w02 = make_float2(u0b.x, u0b.y);
            float2 w03 = make_float2(u0b.z, u0b.w);
            float2 w10 = make_float2(u1a.x, u1a.y);
            float2 w11 = make_float2(u1a.z, u1a.w);
            float2 w12 = make_float2(u1b.x, u1b.y);
            float2 w13 = make_float2(u1b.z, u1b.w);
#pragma unroll
            for (int b = 0; b < BPC; ++b) {
                const float4* ap = reinterpret_cast<const float4*>(actsR + b * KDIM + KREG + kc * 8);
                float4 A0 = ap[0];
                float4 A1 = ap[1];
                float2 p0 = make_float2(A0.x, A0.y);
                float2 p1 = make_float2(A0.z, A0.w);
                float2 p2 = make_float2(A1.x, A1.y);
                float2 p3 = make_float2(A1.z, A1.w);
                acc0[b] = ffma2(w00, p0, acc0[b]);
                acc0[b] = ffma2(w01, p1, acc0[b]);
                acc0[b] = ffma2(w02, p2, acc0[b]);
                acc0[b] = ffma2(w03, p3, acc0[b]);
                acc1[b] = ffma2(w10, p0, acc1[b]);
                acc1[b] = ffma2(w11, p1, acc1[b]);
                acc1[b] = ffma2(w12, p2, acc1[b]);
                acc1[b] = ffma2(w13, p3, acc1[b]);
            }
        }

        // ---- Elementwise: sync-free (writes go to the other buffer) ----
#pragma unroll
        for (int b = 0; b < BPC; ++b) {
            float p0 = acc0[b].x + acc0[b].y + bias0;        // f or o preact
            float p1 = acc1[b].x + acc1[b].y + bias1;        // i or g preact
            float a0 = fmaf(0.5f, tanh_mufu(0.5f * p0), 0.5f);   // sigmoid: fs or os
            float a1 = fmaf(ms, tanh_mufu(mh * p1), mc);         // is (sigmoid) or gt (tanh)
            float o0 = __shfl_xor_sync(0xFFFFFFFFu, a0, 1);
            float o1 = __shfl_xor_sync(0xFFFFFFFFu, a1, 1);
            float fs = role ? o0 : a0;
            float is = role ? o1 : a1;
            float os = role ? a0 : o0;
            float gt = role ? a1 : o1;
            float c  = c_state[b] * fs + gt * is;
            c_state[b] = c;
            float h  = c * os;
            // role0 writes batches 0,1; role1 writes batches 2,3 (identical values)
            if ((b < 2) == (role == 0))
                actsW[b * KDIM + I_DIM + col] = h;
        }
        if (t + 1 < T_LEN) actsW[bx * KDIM + ix] = xnext;    // stage x_{t+1}

        __syncthreads();   // single rendezvous per step

        float* tmp = actsR; actsR = actsW; actsW = tmp;      // swap buffers
    }

    // ---- Final FC: out[b, c] = h[b,:] . Wfc[c,:] + bfc[c] ----
    // After the last swap, actsR holds the final h.
    for (int idx = tid; idx < BPC * C_DIM; idx += NTHREADS) {
        int b  = idx / C_DIM;
        int cc = idx - b * C_DIM;
        float s = bfc[cc];
        const float* hrow = actsR + b * KDIM + I_DIM;
        const float* wrow = Wfc + cc * H_DIM;
#pragma unroll 8
        for (int k = 0; k < H_DIM; ++k)
            s += hrow[k] * wrow[k];
        out[(b0 + b) * C_DIM + cc] = s;
    }
}

extern "C" void kernel_launch(void* const* d_in, const int* in_sizes, int n_in,
                              void* d_out, int out_size)
{
    const float* x   = (const float*)d_in[0];
    const float* Wf  = (const float*)d_in[1];
    const float* bf  = (const float*)d_in[2];
    const float* Wo  = (const float*)d_in[3];
    const float* bo  = (const float*)d_in[4];
    const float* Wi  = (const float*)d_in[5];
    const float* bi  = (const float*)d_in[6];
    const float* Wg  = (const float*)d_in[7];
    const float* bg  = (const float*)d_in[8];
    const float* Wfc = (const float*)d_in[9];
    const float* bfc = (const float*)d_in[10];
    float* out = (float*)d_out;

    static bool attr_set = false;
    if (!attr_set) {
        cudaFuncSetAttribute(lstm_persistent_kernel,
                             cudaFuncAttributeMaxDynamicSharedMemorySize, SM_TOTAL);
        attr_set = true;
    }

    lstm_persistent_kernel<<<NCTAS, NTHREADS, SM_TOTAL>>>(
        x, Wf, bf, Wo, bo, Wi, bi, Wg, bg, Wfc, bfc, out);
}

// round 16
// speedup vs baseline: 4.9012x; 4.4787x over previous
#include <cuda_runtime.h>
#include <cuda_fp16.h>
#include <cstdint>

// x[512,1024,64] f32, W{f,o,i,g}[128,192] f32, b*[128], Wfc[10,128], bfc[10], out[512,10] f32.
#define B_TOT    512
#define T_LEN    1024
#define I_DIM    64
#define H_DIM    128
#define C_DIM    10
#define KDIM     192
#define BPC      4
#define NTHREADS 256
#define NCTAS    (B_TOT / BPC)   // 128

#define AROW     200             // halves per acts row (400B: 100 mod 32 = 4 -> conflict-free)

// m16n8k16 fp16 MMA, fp32 accum, accumulate in place. Base ISA (sm_80+), no 'a' features.
__device__ __forceinline__ void mma16816(float* d, const uint32_t* a, uint32_t b0, uint32_t b1) {
    asm volatile(
        "mma.sync.aligned.m16n8k16.row.col.f32.f16.f16.f32 "
        "{%0,%1,%2,%3}, {%4,%5,%6,%7}, {%8,%9}, {%0,%1,%2,%3};"
        : "+f"(d[0]), "+f"(d[1]), "+f"(d[2]), "+f"(d[3])
        : "r"(a[0]), "r"(a[1]), "r"(a[2]), "r"(a[3]), "r"(b0), "r"(b1));
}

__device__ __forceinline__ float sig_mufu(float z) {
    float r;
    asm("tanh.approx.f32 %0, %1;" : "=f"(r) : "f"(0.5f * z));
    return fmaf(0.5f, r, 0.5f);
}
__device__ __forceinline__ float tanh_mufu(float z) {
    float r;
    asm("tanh.approx.f32 %0, %1;" : "=f"(r) : "f"(z));
    return r;
}

__device__ __forceinline__ uint32_t pack_h2(float lo, float hi) {
    __half2 h = __floats2half2_rn(lo, hi);
    return *reinterpret_cast<uint32_t*>(&h);
}

__global__ void __launch_bounds__(NTHREADS, 1)
lstm_hmma_kernel(const float* __restrict__ x,
                 const float* __restrict__ Wf, const float* __restrict__ bf,
                 const float* __restrict__ Wo, const float* __restrict__ bo,
                 const float* __restrict__ Wi, const float* __restrict__ bi,
                 const float* __restrict__ Wg, const float* __restrict__ bg,
                 const float* __restrict__ Wfc, const float* __restrict__ bfc,
                 float* __restrict__ out)
{
    // Static SMEM: tiny footprint (two acts buffers + final-h fp32 buffer).
    __shared__ __half actsA[8 * AROW];
    __shared__ __half actsB[8 * AROW];
    __shared__ float  hb[BPC * H_DIM];

    const int tid  = threadIdx.x;
    const int w    = tid >> 5;          // warp 0..7: owns gate-rows [16w, 16w+16)
    const int lane = tid & 31;
    const int lg   = lane >> 2;         // group 0..7 -> B column (batch) and A row offset
    const int tt   = lane & 3;          // thread-in-group -> k / batch-pair position
    const int b0g  = blockIdx.x * BPC;

    const int r0 = w * 16 + lg;         // gate-local row 0
    const int r1 = r0 + 8;              // gate-local row 1

    // ---- One-time: build all A fragments (4 gates x 12 k-steps x 4 half2 regs) ----
    // A fragment (m16k16, row-major): a0=A[g][2t,2t+1], a1=A[g+8][...], a2=A[g][2t+8,..], a3=A[g+8][2t+8,..]
    uint32_t afr[4][12][4];
    {
        const float* srcs[4] = {Wf, Wo, Wi, Wg};
#pragma unroll
        for (int gi = 0; gi < 4; ++gi) {
            const float* s = srcs[gi];
#pragma unroll
            for (int ks = 0; ks < 12; ++ks) {
                int k0 = 16 * ks + 2 * tt;
                float2 v0 = __ldg(reinterpret_cast<const float2*>(s + r0 * KDIM + k0));
                float2 v1 = __ldg(reinterpret_cast<const float2*>(s + r1 * KDIM + k0));
                float2 v2 = __ldg(reinterpret_cast<const float2*>(s + r0 * KDIM + k0 + 8));
                float2 v3 = __ldg(reinterpret_cast<const float2*>(s + r1 * KDIM + k0 + 8));
                afr[gi][ks][0] = pack_h2(v0.x, v0.y);
                afr[gi][ks][1] = pack_h2(v1.x, v1.y);
                afr[gi][ks][2] = pack_h2(v2.x, v2.y);
                afr[gi][ks][3] = pack_h2(v3.x, v3.y);
            }
        }
    }

    // Biases for this lane's two rows.
    const float bf0 = __ldg(bf + r0), bf1 = __ldg(bf + r1);
    const float bo0 = __ldg(bo + r0), bo1 = __ldg(bo + r1);
    const float bi0 = __ldg(bi + r0), bi1 = __ldg(bi + r1);
    const float bg0 = __ldg(bg + r0), bg1 = __ldg(bg + r1);

    // ---- Init: zero both acts buffers (batches 4..7 stay zero forever) ----
    for (int i = tid; i < 8 * AROW / 2; i += NTHREADS) {
        reinterpret_cast<uint32_t*>(actsA)[i] = 0;
        reinterpret_cast<uint32_t*>(actsB)[i] = 0;
    }

    // x staging slot: thread -> (batch bb, feature ff)
    const int bb = tid >> 6;            // 0..3
    const int ff = tid & 63;            // 0..63
    const float* xp = x + (size_t)(b0g + bb) * T_LEN * I_DIM + ff;
    __syncthreads();
    actsA[bb * AROW + ff] = __float2half_rn(__ldg(xp));   // x(t=0)
    __syncthreads();

    // c-state: lane (lg,tt) owns rows {r0,r1} x batches {2tt, 2tt+1}; valid only when tt<2.
    float c_st[4] = {0.f, 0.f, 0.f, 0.f};

    for (int t = 0; t < T_LEN; ++t) {
        const __half* aR = (t & 1) ? actsB : actsA;
        __half*       aW = (t & 1) ? actsA : actsB;

        float xval = 0.0f;
        if (t + 1 < T_LEN) xval = __ldg(xp + (size_t)(t + 1) * I_DIM);

        float acc[4][4];
#pragma unroll
        for (int gi = 0; gi < 4; ++gi)
#pragma unroll
            for (int q = 0; q < 4; ++q) acc[gi][q] = 0.0f;

        // ---- GEMM: 12 k-steps, one B fragment load shared by the 4 gate MMAs ----
#pragma unroll
        for (int ks = 0; ks < 12; ++ks) {
            // B fragment (k16n8 col): b0 = B[2t,2t+1][g], b1 = B[2t+8,2t+9][g]; col g = batch.
            const uint32_t* brow = reinterpret_cast<const uint32_t*>(aR + lg * AROW + 16 * ks);
            uint32_t b0 = brow[tt];         // halves (2tt, 2tt+1)
            uint32_t b1 = brow[tt + 4];     // halves (2tt+8, 2tt+9)
            mma16816(acc[0], afr[0][ks], b0, b1);
            mma16816(acc[1], afr[1][ks], b0, b1);
            mma16816(acc[2], afr[2][ks], b0, b1);
            mma16816(acc[3], afr[3][ks], b0, b1);
        }

        // ---- Epilogue: D lane layout: q0=(r0,c0) q1=(r0,c1) q2=(r1,c0) q3=(r1,c1), c0=2tt ----
#pragma unroll
        for (int q = 0; q < 4; ++q) {
            const int   row = (q < 2) ? r0 : r1;
            const float bfv = (q < 2) ? bf0 : bf1;
            const float bov = (q < 2) ? bo0 : bo1;
            const float biv = (q < 2) ? bi0 : bi1;
            const float bgv = (q < 2) ? bg0 : bg1;
            float fs = sig_mufu(acc[0][q] + bfv);
            float os = sig_mufu(acc[1][q] + bov);
            float is = sig_mufu(acc[2][q] + biv);
            float gt = tanh_mufu(acc[3][q] + bgv);
            float c  = c_st[q] * fs + gt * is;
            c_st[q] = c;
            float h = c * os;                     // reference: no tanh on c
            if (tt < 2) {                         // batches 0..3 only
                int batch = 2 * tt + (q & 1);
                aW[batch * AROW + I_DIM + row] = __float2half_rn(h);
                if (t == T_LEN - 1)
                    hb[batch * H_DIM + row] = h;  // fp32 h for the final FC
            }
        }

        if (t + 1 < T_LEN)
            aW[bb * AROW + ff] = __float2half_rn(xval);   // stage x(t+1)

        __syncthreads();   // single rendezvous per step
    }

    // ---- Final FC: out[b, cc] = h[b,:] . Wfc[cc,:] + bfc[cc] ----
    if (tid < BPC * C_DIM) {
        int b  = tid / C_DIM;
        int cc = tid - b * C_DIM;
        float s = __ldg(bfc + cc);
        const float* hrow = hb + b * H_DIM;
        const float* wrow = Wfc + cc * H_DIM;
#pragma unroll 8
        for (int k = 0; k < H_DIM; ++k) s += hrow[k] * wrow[k];
        out[(b0g + b) * C_DIM + cc] = s;
    }
}

extern "C" void kernel_launch(void* const* d_in, const int* in_sizes, int n_in,
                              void* d_out, int out_size)
{
    const float* x   = (const float*)d_in[0];
    const float* Wf  = (const float*)d_in[1];
    const float* bf  = (const float*)d_in[2];
    const float* Wo  = (const float*)d_in[3];
    const float* bo  = (const float*)d_in[4];
    const float* Wi  = (const float*)d_in[5];
    const float* bi  = (const float*)d_in[6];
    const float* Wg  = (const float*)d_in[7];
    const float* bg  = (const float*)d_in[8];
    const float* Wfc = (const float*)d_in[9];
    const float* bfc = (const float*)d_in[10];
    float* out = (float*)d_out;

    lstm_hmma_kernel<<<NCTAS, NTHREADS>>>(
        x, Wf, bf, Wo, bo, Wi, bi, Wg, bg, Wfc, bfc, out);
}